// round 14
// baseline (speedup 1.0000x reference)
#include <cuda_runtime.h>
#include <cuda_bf16.h>
#include <math_constants.h>

// CaptionDetectionTargetLayer: B=8, N=4096, G=512, C=15
// Outputs (concat float32): rois[B,200,4] | deltas[B,200,4] | caps[B,200,15] | scores[B,200]

#define T_ROIS   200
#define POS_MAX  66
#define NB       4096
#define MAXG     512
#define ZL       8            // z-lanes per proposal (within warp)
#define GP       64           // gts per z-lane (512/8)
#define PPB      32           // proposals per block
#define K1_BLOCK 256          // PPB * ZL
#define NEG_T0   96           // first thread handling negatives in select phase

__device__ unsigned char g_flags[8 * NB];   // 0=invalid, 1=neg, 2=pos
__device__ short         g_argm [8 * NB];   // argmax gt index per proposal
__device__ int           g_cnt  [8];        // per-image completion counters (0-init)

// ---------------------------------------------------------------------------
// Fused kernel: 128 iou blocks + 1 zero-fill block per image. The last block
// to finish an image (threadFenceReduction pattern) runs the select phase
// inline, overlapping selects with remaining iou work of other images.
//
// iou phase (proven R12): gt dim split across 8 lanes of a warp with STRIDED
// mapping j = jj*8 + z (8 consecutive float4 per iteration -> conflict-free
// LDS). Division-free ratio compare with guard band; rare in-band cases take
// an exact f64-product compare. One __fdiv_rn per lane reproduces the
// reference's rounded quotient before the shfl merge (strict >, lower idx).
// ---------------------------------------------------------------------------
__global__ void fused_kernel(const float4* __restrict__ proposals,
                             const float4* __restrict__ gt,
                             const int*    __restrict__ caps,
                             const float*  __restrict__ scores,
                             int N, int G, int C, int B,
                             float* __restrict__ out)
{
    const int b = blockIdx.y;

    // output sections for image b
    float* rois    = out + (size_t)b * T_ROIS * 4;
    float* deltas  = out + (size_t)B * T_ROIS * 4 + (size_t)b * T_ROIS * 4;
    float* ocaps   = out + (size_t)2 * B * T_ROIS * 4 + (size_t)b * T_ROIS * C;
    float* oscores = out + (size_t)B * T_ROIS * (8 + C) + (size_t)b * T_ROIS;

    __shared__ float4 sg[MAXG];
    __shared__ float  sa2[MAXG];    // gt area; +inf marks invalid gt (never wins)
    __shared__ int    swarp[9];
    __shared__ int    spos[POS_MAX];
    __shared__ int    sneg[T_ROIS];
    __shared__ int    sgi [POS_MAX];
    __shared__ int    s_last;

    if (blockIdx.x == gridDim.x - 1) {
        // zero-fill this image's output slices (harness poisons the buffer)
        for (int k = threadIdx.x; k < T_ROIS * 4; k += K1_BLOCK) { rois[k] = 0.0f; deltas[k] = 0.0f; }
        for (int k = threadIdx.x; k < T_ROIS * C; k += K1_BLOCK) ocaps[k] = 0.0f;
        for (int k = threadIdx.x; k < T_ROIS;     k += K1_BLOCK) oscores[k] = 0.0f;
    } else {
        // ---- iou phase ----
        for (int j = threadIdx.x; j < G; j += K1_BLOCK) {
            float4 g = gt[(size_t)b * G + j];
            sg[j] = g;
            float a2 = (g.z - g.x) * (g.w - g.y);
            bool vg  = (fabsf(g.x) + fabsf(g.y) + fabsf(g.z) + fabsf(g.w)) > 0.0f;
            sa2[j] = vg ? a2 : CUDART_INF_F;
        }
        __syncthreads();

        const int z  = threadIdx.x & (ZL - 1);      // 0..7 within 8-lane group
        const int pl = threadIdx.x >> 3;            // proposal-local 0..31
        const int i  = blockIdx.x * PPB + pl;

        float4 p  = proposals[(size_t)b * N + i];   // broadcast across 8 lanes
        float  a1 = (p.z - p.x) * (p.w - p.y);
        bool   vp = (fabsf(p.x) + fabsf(p.y) + fabsf(p.z) + fabsf(p.w)) > 0.0f;

        float best_inter = 0.0f;
        float best_d     = 1.0f;
        int   bi         = z;                       // first j this lane visits

        #pragma unroll 4
        for (int jj = 0; jj < GP; ++jj) {
            int j = (jj << 3) + z;                  // strided: lanes -> consecutive
            float4 g  = sg[j];
            float  a2 = sa2[j];
            float y1 = fmaxf(p.x, g.x);
            float x1 = fmaxf(p.y, g.y);
            float y2 = fminf(p.z, g.z);
            float x2 = fminf(p.w, g.w);
            float inter = fmaxf(x2 - x1, 0.0f) * fmaxf(y2 - y1, 0.0f);
            float uni   = a1 + a2 - inter;          // +inf for invalid gt
            float d     = uni > 0.0f ? uni : 1.0f;

            float lhs = __fmul_rn(inter, best_d);
            float rhs = __fmul_rn(best_inter, d);   // inf or NaN for invalid gt
            if (lhs > __fmul_rn(rhs, 1.000001f)) {  // definitely greater
                best_inter = inter; best_d = d; bi = j;
            } else if (lhs > __fmul_rn(rhs, 0.999999f)) {
                // ambiguous band (rare): exact compare, f32*f32 exact in f64
                double dl = (double)inter * (double)best_d;
                double dr = (double)best_inter * (double)d;
                if (dl > dr) { best_inter = inter; best_d = d; bi = j; }
            }
        }

        float iou = __fdiv_rn(best_inter, best_d);  // reference's rounded value
        int   idx = bi;

        #pragma unroll
        for (int m = 1; m < ZL; m <<= 1) {
            float o_iou = __shfl_xor_sync(0xFFFFFFFFu, iou, m);
            int   o_idx = __shfl_xor_sync(0xFFFFFFFFu, idx, m);
            bool take = (o_iou > iou) || (o_iou == iou && o_idx < idx);
            iou = take ? o_iou : iou;
            idx = take ? o_idx : idx;
        }

        if (z == 0) {
            g_flags[b * N + i] = vp ? (iou >= 0.5f ? 2 : 1) : 0;
            g_argm [b * N + i] = (short)idx;
        }
    }

    // ---- completion handshake: last block of image b runs select inline ----
    __threadfence();
    if (threadIdx.x == 0) {
        int done = atomicAdd(&g_cnt[b], 1);
        int last = (done == (int)gridDim.x - 1);
        s_last = last;
        if (last) g_cnt[b] = 0;                     // reset for next replay
    }
    __syncthreads();
    if (!s_last) return;

    // =======================================================================
    // select phase (256 threads): 16 proposals per thread
    // =======================================================================
    const int t    = threadIdx.x;
    const int lane = t & 31;
    const int wid  = t >> 5;

    // load 16 flags (one uint4), bypass L1 (written by other SMs)
    uint4 w4 = __ldcg((const uint4*)(g_flags + b * N) + t);
    unsigned char f[16];
    #pragma unroll
    for (int k = 0; k < 4;  ++k) f[k]      = (w4.x >> (8 * k)) & 0xFF;
    #pragma unroll
    for (int k = 0; k < 4;  ++k) f[4 + k]  = (w4.y >> (8 * k)) & 0xFF;
    #pragma unroll
    for (int k = 0; k < 4;  ++k) f[8 + k]  = (w4.z >> (8 * k)) & 0xFF;
    #pragma unroll
    for (int k = 0; k < 4;  ++k) f[12 + k] = (w4.w >> (8 * k)) & 0xFF;

    int pc = 0, nc = 0;
    #pragma unroll
    for (int k = 0; k < 16; ++k) { pc += (f[k] == 2); nc += (f[k] == 1); }

    // packed (pos<<16 | neg) inclusive warp scan over 256 threads (8 warps)
    int v = (pc << 16) | nc;
    int incl = v;
    #pragma unroll
    for (int off = 1; off < 32; off <<= 1) {
        int n = __shfl_up_sync(0xFFFFFFFFu, incl, off);
        if (lane >= off) incl += n;
    }
    if (lane == 31) swarp[wid] = incl;
    __syncthreads();
    if (wid == 0 && lane < 8) {
        int wv = swarp[lane];
        int wincl = wv;
        #pragma unroll
        for (int off = 1; off < 8; off <<= 1) {
            int n = __shfl_up_sync(0x000000FFu, wincl, off);
            if (lane >= off) wincl += n;
        }
        swarp[lane] = wincl - wv;                   // exclusive warp prefix
        if (lane == 7) swarp[8] = wincl;            // grand total
    }
    __syncthreads();

    int excl   = swarp[wid] + incl - v;
    int total  = swarp[8];
    int p_base = excl >> 16;
    int n_base = excl & 0xFFFF;
    int pos_total = total >> 16;
    int neg_total = total & 0xFFFF;

    int pos_cnt = min(pos_total, POS_MAX);
    // XLA div-by-const -> mul-by-reciprocal: 66*round(1/0.33)=199.99999347->200.0f
    float rcp = __fdiv_rn(1.0f, 0.33f);
    int neg_target = (int)__fmul_rn((float)pos_cnt, rcp) - pos_cnt;
    int neg_cnt = min(min(neg_target, neg_total), T_ROIS - pos_cnt);
    if (neg_cnt < 0) neg_cnt = 0;

    // stage selected roi indices (ascending order preserved)
    {
        int pr = p_base, nr = n_base;
        int base = t * 16;
        #pragma unroll
        for (int k = 0; k < 16; ++k) {
            int i = base + k;
            if (f[k] == 2) {
                if (pr < pos_cnt) spos[pr] = i;
                pr++;
            } else if (f[k] == 1) {
                if (nr < neg_cnt) sneg[nr] = i;
                nr++;
            }
        }
    }
    __syncthreads();

    float4* rois4   = (float4*)rois;
    float4* deltas4 = (float4*)deltas;

    // positives (t < pos_cnt <= 66) and negatives (t in [96, 96+neg_cnt), 
    // neg_cnt <= 134 -> max thread 229) scatter concurrently, disjoint ranges
    if (t < pos_cnt) {
        int i = spos[t];
        float4 p = proposals[(size_t)b * N + i];
        int gi = __ldcg(g_argm + b * N + i);
        sgi[t] = gi;
        float4 g = gt[(size_t)b * G + gi];

        rois4[t] = p;

        float h  = p.z - p.x, w  = p.w - p.y;
        float cy = p.x + 0.5f * h, cx = p.y + 0.5f * w;
        float gh = g.z - g.x, gw = g.w - g.y;
        float gcy = g.x + 0.5f * gh, gcx = g.y + 0.5f * gw;
        float4 d4;
        d4.x = __fdiv_rn(__fdiv_rn(gcy - cy, h), 0.1f);
        d4.y = __fdiv_rn(__fdiv_rn(gcx - cx, w), 0.1f);
        d4.z = __fdiv_rn(logf(__fdiv_rn(gh, h)), 0.2f);
        d4.w = __fdiv_rn(logf(__fdiv_rn(gw, w)), 0.2f);
        deltas4[t] = d4;

        oscores[t] = scores[(size_t)b * G + gi];
    } else if (t >= NEG_T0 && (t - NEG_T0) < neg_cnt) {
        int s = t - NEG_T0;
        int i = sneg[s];
        rois4[pos_cnt + s] = proposals[(size_t)b * N + i];
    }
    __syncthreads();

    // cooperative coalesced caption gather: pos_cnt*C <= 990 elements
    for (int idx = t; idx < pos_cnt * C; idx += K1_BLOCK) {
        int slot = idx / C;
        int c    = idx - slot * C;
        ocaps[slot * C + c] = (float)caps[((size_t)b * G + sgi[slot]) * C + c];
    }
}

// ---------------------------------------------------------------------------
extern "C" void kernel_launch(void* const* d_in, const int* in_sizes, int n_in,
                              void* d_out, int out_size)
{
    const float4* proposals = (const float4*)d_in[0];
    const float4* gt_boxes  = (const float4*)d_in[1];
    const int*    captions  = (const int*)  d_in[2];
    const float*  scores    = (const float*)d_in[3];
    float*        out       = (float*)d_out;

    const int N = NB;
    int B = in_sizes[0] / (4 * N);         // 8
    int G = in_sizes[3] / B;               // 512
    int C = in_sizes[2] / in_sizes[3];     // 15

    dim3 grid(N / PPB + 1, B);             // 128 iou blocks + 1 zero-fill per image
    fused_kernel<<<grid, K1_BLOCK>>>(proposals, gt_boxes, captions, scores,
                                     N, G, C, B, out);
}

// round 16
// speedup vs baseline: 1.2113x; 1.2113x over previous
#include <cuda_runtime.h>
#include <cuda_bf16.h>

// CaptionDetectionTargetLayer: B=8, N=4096, G=512, C=15
// Outputs (concat float32): rois[B,200,4] | deltas[B,200,4] | caps[B,200,15] | scores[B,200]

#define T_ROIS   200
#define POS_MAX  66
#define NB       4096
#define MAXG     512
#define ZL       8            // z-lanes per proposal (within warp)
#define GP       64           // gts per z-lane (512/8)
#define PPB      32           // proposals per block
#define K1_BLOCK 256          // PPB * ZL
#define K2_BLOCK 1024

__device__ unsigned char g_flags[8 * NB];   // 0=invalid, 1=neg, 2=pos
__device__ short         g_argm [8 * NB];   // argmax gt index per proposal

// ---------------------------------------------------------------------------
// Kernel 1: per-proposal masked IoU row-max + argmax, gt dim split across
// 8 lanes of a warp, STRIDED mapping j = jj*8 + z (conflict-free LDS).
// Invalid gts are stored as sentinel box (2,2,2,2)/area 0 -> inter = 0 ->
// can never be selected, which removes the per-pair d-select (uni used
// directly: any winning pair has inter>0 hence uni >= max(area) > 0).
// Division-free ratio compare with guard band; rare in-band cases take an
// exact f64-product compare. One __fdiv_rn per lane reproduces the
// reference's rounded quotient before the shfl merge (strict >, lower idx).
// Extra block column zero-fills the output concurrently.
// ---------------------------------------------------------------------------
__global__ void iou_max_kernel(const float4* __restrict__ proposals,
                               const float4* __restrict__ gt,
                               int N, int G, int C, int B,
                               float* __restrict__ out)
{
    const int b = blockIdx.y;

    if (blockIdx.x == gridDim.x - 1) {
        // zero-fill this image's output slices (harness poisons the buffer)
        float* rois    = out + (size_t)b * T_ROIS * 4;
        float* deltas  = out + (size_t)B * T_ROIS * 4 + (size_t)b * T_ROIS * 4;
        float* ocaps   = out + (size_t)2 * B * T_ROIS * 4 + (size_t)b * T_ROIS * C;
        float* oscores = out + (size_t)B * T_ROIS * (8 + C) + (size_t)b * T_ROIS;
        for (int k = threadIdx.x; k < T_ROIS * 4; k += K1_BLOCK) { rois[k] = 0.0f; deltas[k] = 0.0f; }
        for (int k = threadIdx.x; k < T_ROIS * C; k += K1_BLOCK) ocaps[k] = 0.0f;
        for (int k = threadIdx.x; k < T_ROIS;     k += K1_BLOCK) oscores[k] = 0.0f;
        return;
    }

    __shared__ float4 sg[MAXG];
    __shared__ float  sa2[MAXG];

    for (int j = threadIdx.x; j < G; j += K1_BLOCK) {
        float4 g = gt[(size_t)b * G + j];
        bool vg  = (fabsf(g.x) + fabsf(g.y) + fabsf(g.z) + fabsf(g.w)) > 0.0f;
        if (!vg) g = make_float4(2.0f, 2.0f, 2.0f, 2.0f);   // sentinel: inter=0
        sg[j]  = g;
        sa2[j] = vg ? (g.z - g.x) * (g.w - g.y) : 0.0f;
    }
    __syncthreads();

    const int z  = threadIdx.x & (ZL - 1);          // 0..7 within 8-lane group
    const int pl = threadIdx.x >> 3;                // proposal-local 0..31
    const int i  = blockIdx.x * PPB + pl;

    float4 p  = proposals[(size_t)b * N + i];       // broadcast across 8 lanes
    float  a1 = (p.z - p.x) * (p.w - p.y);
    bool   vp = (fabsf(p.x) + fabsf(p.y) + fabsf(p.z) + fabsf(p.w)) > 0.0f;

    // best ratio = best_inter / best_d, init 0/1 (== IoU 0)
    float best_inter = 0.0f;
    float best_d     = 1.0f;
    int   bi         = z;                           // first j this lane visits

    #pragma unroll 4
    for (int jj = 0; jj < GP; ++jj) {
        int j = (jj << 3) + z;                      // strided: lanes -> consecutive
        float4 g  = sg[j];
        float  a2 = sa2[j];
        float y1 = fmaxf(p.x, g.x);
        float x1 = fmaxf(p.y, g.y);
        float y2 = fminf(p.z, g.z);
        float x2 = fminf(p.w, g.w);
        float inter = fmaxf(x2 - x1, 0.0f) * fmaxf(y2 - y1, 0.0f);
        float uni   = a1 + a2 - inter;              // >0 whenever inter>0

        // compare inter/uni vs best_inter/best_d (both nonnegative)
        float lhs = __fmul_rn(inter, best_d);
        float rhs = __fmul_rn(best_inter, uni);
        if (lhs > __fmul_rn(rhs, 1.000001f)) {      // definitely greater
            best_inter = inter; best_d = uni; bi = j;
        } else if (lhs > __fmul_rn(rhs, 0.999999f)) {
            // ambiguous band (rare): exact compare, f32*f32 exact in f64
            double dl = (double)inter * (double)best_d;
            double dr = (double)best_inter * (double)uni;
            if (dl > dr) { best_inter = inter; best_d = uni; bi = j; }
        }
    }

    // per-lane rounded quotient (the reference's compared value)
    float iou = __fdiv_rn(best_inter, best_d);
    int   idx = bi;

    // merge across the 8 z-lanes: strict >, lower global idx wins ties
    #pragma unroll
    for (int m = 1; m < ZL; m <<= 1) {
        float o_iou = __shfl_xor_sync(0xFFFFFFFFu, iou, m);
        int   o_idx = __shfl_xor_sync(0xFFFFFFFFu, idx, m);
        bool take = (o_iou > iou) || (o_iou == iou && o_idx < idx);
        iou = take ? o_iou : iou;
        idx = take ? o_idx : idx;
    }

    if (z == 0) {
        g_flags[b * N + i] = vp ? (iou >= 0.5f ? 2 : 1) : 0;
        g_argm [b * N + i] = (short)idx;
    }
}

// ---------------------------------------------------------------------------
// Kernel 2: per-image ordered compaction + parallel staged scatter.
// One block of 1024 threads per image. After ONE staging barrier, three
// independent jobs run concurrently: pos roi/delta scatter (t < pos_cnt),
// neg roi scatter (t >= 512), caption+score gather (all threads, reads
// g_argm[spos[slot]] directly -- no second barrier).
// ---------------------------------------------------------------------------
__global__ void select_kernel(const float4* __restrict__ proposals,
                              const float4* __restrict__ gt,
                              const int*    __restrict__ caps,
                              const float*  __restrict__ scores,
                              int N, int G, int C, int B,
                              float* __restrict__ out)
{
    const int b    = blockIdx.x;
    const int t    = threadIdx.x;
    const int lane = t & 31;
    const int wid  = t >> 5;

    // load 4 flags as one word; count pos/neg
    unsigned int fl4 = ((const unsigned int*)(g_flags + b * N))[t];
    unsigned char f[4];
    int pc = 0, nc = 0;
    #pragma unroll
    for (int k = 0; k < 4; ++k) {
        f[k] = (fl4 >> (8 * k)) & 0xFF;
        pc += (f[k] == 2);
        nc += (f[k] == 1);
    }

    // packed (pos<<16 | neg) inclusive warp scan
    int v = (pc << 16) | nc;
    int incl = v;
    #pragma unroll
    for (int off = 1; off < 32; off <<= 1) {
        int n = __shfl_up_sync(0xFFFFFFFFu, incl, off);
        if (lane >= off) incl += n;
    }

    __shared__ int swarp[33];
    if (lane == 31) swarp[wid] = incl;
    __syncthreads();
    if (wid == 0) {
        int wv = swarp[lane];
        int wincl = wv;
        #pragma unroll
        for (int off = 1; off < 32; off <<= 1) {
            int n = __shfl_up_sync(0xFFFFFFFFu, wincl, off);
            if (lane >= off) wincl += n;
        }
        swarp[lane] = wincl - wv;
        if (lane == 31) swarp[32] = wincl;
    }
    __syncthreads();

    int excl   = swarp[wid] + incl - v;
    int total  = swarp[32];
    int p_base = excl >> 16;
    int n_base = excl & 0xFFFF;
    int pos_total = total >> 16;
    int neg_total = total & 0xFFFF;

    int pos_cnt = min(pos_total, POS_MAX);
    // XLA div-by-const -> mul-by-reciprocal: 66*round(1/0.33)=199.99999347->200.0f
    float rcp = __fdiv_rn(1.0f, 0.33f);
    int neg_target = (int)__fmul_rn((float)pos_cnt, rcp) - pos_cnt;
    int neg_cnt = min(min(neg_target, neg_total), T_ROIS - pos_cnt);
    if (neg_cnt < 0) neg_cnt = 0;

    // stage selected roi indices (ascending order preserved)
    __shared__ int spos[POS_MAX];
    __shared__ int sneg[T_ROIS];
    {
        int pr = p_base, nr = n_base;
        int base = t * 4;
        #pragma unroll
        for (int k = 0; k < 4; ++k) {
            int i = base + k;
            if (f[k] == 2) {
                if (pr < pos_cnt) spos[pr] = i;
                pr++;
            } else if (f[k] == 1) {
                if (nr < neg_cnt) sneg[nr] = i;
                nr++;
            }
        }
    }
    __syncthreads();

    // output sections
    float* rois    = out + (size_t)b * T_ROIS * 4;
    float* deltas  = out + (size_t)B * T_ROIS * 4 + (size_t)b * T_ROIS * 4;
    float* ocaps   = out + (size_t)2 * B * T_ROIS * 4 + (size_t)b * T_ROIS * C;
    float* oscores = out + (size_t)B * T_ROIS * (8 + C) + (size_t)b * T_ROIS;
    float4* rois4   = (float4*)rois;
    float4* deltas4 = (float4*)deltas;

    // -- job A: positive roi + delta scatter (t < pos_cnt <= 66) --
    if (t < pos_cnt) {
        int i = spos[t];
        float4 p = proposals[(size_t)b * N + i];
        int gi = g_argm[b * N + i];
        float4 g = gt[(size_t)b * G + gi];

        rois4[t] = p;

        float h  = p.z - p.x, w  = p.w - p.y;
        float cy = p.x + 0.5f * h, cx = p.y + 0.5f * w;
        float gh = g.z - g.x, gw = g.w - g.y;
        float gcy = g.x + 0.5f * gh, gcx = g.y + 0.5f * gw;
        float4 d4;
        d4.x = __fdiv_rn(__fdiv_rn(gcy - cy, h), 0.1f);
        d4.y = __fdiv_rn(__fdiv_rn(gcx - cx, w), 0.1f);
        d4.z = __fdiv_rn(logf(__fdiv_rn(gh, h)), 0.2f);
        d4.w = __fdiv_rn(logf(__fdiv_rn(gw, w)), 0.2f);
        deltas4[t] = d4;
    } else if (t >= 512 && (t - 512) < neg_cnt) {
        // -- job B: negative roi scatter (disjoint warp range) --
        int s = t - 512;
        int i = sneg[s];
        rois4[pos_cnt + s] = proposals[(size_t)b * N + i];
    }

    // -- job C: caption + score gather, concurrent with A/B (no barrier) --
    // 16 elements per positive slot: c in [0,15) -> caption, c == 15 -> score
    for (int idx = t; idx < pos_cnt * 16; idx += K2_BLOCK) {
        int slot = idx >> 4;
        int c    = idx & 15;
        int gi   = g_argm[b * N + spos[slot]];
        if (c < C)
            ocaps[slot * C + c] = (float)caps[((size_t)b * G + gi) * C + c];
        else
            oscores[slot] = scores[(size_t)b * G + gi];
    }
}

// ---------------------------------------------------------------------------
extern "C" void kernel_launch(void* const* d_in, const int* in_sizes, int n_in,
                              void* d_out, int out_size)
{
    const float4* proposals = (const float4*)d_in[0];
    const float4* gt_boxes  = (const float4*)d_in[1];
    const int*    captions  = (const int*)  d_in[2];
    const float*  scores    = (const float*)d_in[3];
    float*        out       = (float*)d_out;

    const int N = NB;
    int B = in_sizes[0] / (4 * N);         // 8
    int G = in_sizes[3] / B;               // 512
    int C = in_sizes[2] / in_sizes[3];     // 15

    dim3 grid1(N / PPB + 1, B);            // +1 block column zero-fills output
    iou_max_kernel<<<grid1, K1_BLOCK>>>(proposals, gt_boxes, N, G, C, B, out);

    select_kernel<<<B, K2_BLOCK>>>(proposals, gt_boxes, captions, scores,
                                   N, G, C, B, out);
}